// round 15
// baseline (speedup 1.0000x reference)
#include <cuda_runtime.h>
#include <cstdint>

// Correlation cost volume: B=8, C=128, H=W=128, max_disp=4 -> 81 displacements.
// out[b, dy*9+dx, y, x] = (1/C) sum_c in1[b,c,y,x] * in2[b,c,y+dy-4,x+dx-4] (zero pad)
//
// R14 = R11 (scalar FFMA core, quad-transposed smem, CH=8, 2-stage cp.async)
//       + branch-free closed-form loader (unrolled k, divmod10 via select)
//       + interior/edge template specialization (only 4/64 ytiles need bounds).

#define BB 8
#define CC 128
#define HH 128
#define WW 128
#define MD 4
#define ND 9
#define NDD 81
#define TY 2
#define CH 8
#define NCHUNK (CC / CH)        // 16
#define THREADS 288             // 9 warps
#define S2_RI (TY + 2 * MD)     // 10

#define S1_ROWQ 32              // quads per in1 row
#define S2_ROWQ 34              // quads per padded in2 row (136 floats)
#define S1_Q (CH * TY * S1_ROWQ)        // 512
#define S2_Q (CH * S2_RI * S2_ROWQ)     // 2720
#define STAGE_Q (S1_Q + S2_Q)           // 3232
#define STAGE_BYTES (STAGE_Q * 16)      // 51712
#define SMEM_BYTES (2 * STAGE_BYTES)    // 103424

__device__ __forceinline__ void cp16(uint32_t dst, const float* src, int srcsz) {
    asm volatile("cp.async.cg.shared.global [%0], [%1], 16, %2;\n"
                 :: "r"(dst), "l"(src), "r"(srcsz));
}
__device__ __forceinline__ void cp_commit() {
    asm volatile("cp.async.commit_group;\n");
}
#define CP_WAIT(n) asm volatile("cp.async.wait_group %0;\n" :: "n"(n))

// Load channel-chunk cc into stage at shared byte address sbase.
// EDGE=false: all 10 tile rows are in-bounds (ytiles with y0 in [4,122]).
template <bool EDGE>
__device__ __forceinline__ void load_chunk(
    int cc, uint32_t sbase,
    const float* __restrict__ in1, const float* __restrict__ in2,
    int b, int y0, int w, int lane)
{
    const size_t cbase = (size_t)(b * CC + cc * CH) * (HH * WW);
    const float* g1 = in1 + cbase;
    const float* g2 = in2 + cbase;

    // ---- in1: rows r = w and w+9 (r < 16); lane -> quad = lane ----
    {
        const uint32_t dslot = (uint32_t)((lane & 1) * 16 + (lane >> 1));
        int c = w >> 1, row = w & 1;
        cp16(sbase + 16u * ((uint32_t)(c * TY + row) * S1_ROWQ + dslot),
             g1 + ((size_t)c * HH + y0 + row) * WW + 4 * lane, 16);
        int r2 = w + ND;
        if (r2 < CH * TY) {
            c = r2 >> 1; row = r2 & 1;
            cp16(sbase + 16u * ((uint32_t)(c * TY + row) * S1_ROWQ + dslot),
                 g1 + ((size_t)c * HH + y0 + row) * WW + 4 * lane, 16);
        }
    }

    // ---- in2: rows row = w + 9k, k = 0..8; interior quads q = lane+1 ----
    {
        const int q = lane + 1;
        const uint32_t fslot = (uint32_t)((q & 1) * 17 + (q >> 1));
        const uint32_t s2b = sbase + 16u * S1_Q + 16u * fslot;
#pragma unroll
        for (int k = 0; k < 9; ++k) {
            const int row = w + ND * k;                 // 0..80
            if (k == 8 && row >= CH * S2_RI) continue;  // w==8, row==80
            const int c  = (w >= k) ? k : k - 1;        // row / 10
            const int ri = row - S2_RI * c;             // row % 10
            const int gy = y0 - MD + ri;
            const uint32_t dst = s2b + (uint32_t)row * (16u * S2_ROWQ);
            if (EDGE) {
                int ok = ((unsigned)gy < HH) ? 16 : 0;
                const float* src = ok ? (g2 + ((size_t)c * HH + gy) * WW + 4 * lane)
                                      : g2;
                cp16(dst, src, ok);
            } else {
                cp16(dst, g2 + ((size_t)c * HH + gy) * WW + 4 * lane, 16);
            }
        }
    }
}

__device__ __forceinline__ void load_chunk_d(
    bool edge, int cc, uint32_t sbase,
    const float* __restrict__ in1, const float* __restrict__ in2,
    int b, int y0, int w, int lane)
{
    if (edge) load_chunk<true >(cc, sbase, in1, in2, b, y0, w, lane);
    else      load_chunk<false>(cc, sbase, in1, in2, b, y0, w, lane);
}

__global__ __launch_bounds__(THREADS, 2)
void corr_kernel(const float* __restrict__ in1,
                 const float* __restrict__ in2,
                 float* __restrict__ out)
{
    extern __shared__ float sm[];
    const uint32_t smb = (uint32_t)__cvta_generic_to_shared(sm);

    const int y0 = blockIdx.x * TY;
    const int b  = blockIdx.y;
    const bool edge = (y0 < MD) | (y0 > HH - TY - MD);

    const int tid  = threadIdx.x;
    const int w    = tid >> 5;          // dy index 0..8
    const int lane = tid & 31;
    const int tr   = lane >> 4;         // output row 0..1
    const int lb   = lane & 15;         // pixels x = 8*lb + j
    const int ri   = tr + w;            // in2 tile row 0..9

    // pre-zero always-padding edge quads (slots 0 and 33) in both stages
    for (int i = tid; i < 2 * CH * S2_RI * 2; i += THREADS) {   // 320
        int st  = i / (CH * S2_RI * 2);
        int rem = i - st * (CH * S2_RI * 2);
        float4* p = reinterpret_cast<float4*>(sm) +
                    (size_t)st * STAGE_Q + S1_Q + (rem >> 1) * S2_ROWQ + (rem & 1) * 33;
        *p = make_float4(0.f, 0.f, 0.f, 0.f);
    }

    float acc[ND][8];
#pragma unroll
    for (int dx = 0; dx < ND; ++dx)
#pragma unroll
        for (int j = 0; j < 8; ++j) acc[dx][j] = 0.0f;

    load_chunk_d(edge, 0, smb, in1, in2, b, y0, w, lane);
    cp_commit();

    for (int cc = 0; cc < NCHUNK; ++cc) {
        CP_WAIT(0);          // chunk cc resident (this thread's copies)
        __syncthreads();     // all copies visible; prev compute finished (WAR)

        if (cc + 1 < NCHUNK)
            load_chunk_d(edge, cc + 1, smb + ((cc + 1) & 1) * STAGE_BYTES,
                         in1, in2, b, y0, w, lane);
        cp_commit();

        const float4* st4 = reinterpret_cast<const float4*>(sm) +
                            (size_t)(cc & 1) * STAGE_Q;
#pragma unroll
        for (int c = 0; c < CH; ++c) {
            const float4* ar = st4 + (c * TY + tr) * S1_ROWQ;
            const float4* fr = st4 + S1_Q + (c * S2_RI + ri) * S2_ROWQ;

            float4 A0 = ar[lb];             // pixels 8lb+0..3
            float4 A1 = ar[16 + lb];        // pixels 8lb+4..7
            float4 F0 = fr[lb];             // f[0..3]
            float4 F1 = fr[17 + lb];        // f[4..7]
            float4 F2 = fr[lb + 1];         // f[8..11]
            float4 F3 = fr[17 + lb + 1];    // f[12..15]

            const float a[8]  = { A0.x, A0.y, A0.z, A0.w,
                                  A1.x, A1.y, A1.z, A1.w };
            const float f[16] = { F0.x, F0.y, F0.z, F0.w,
                                  F1.x, F1.y, F1.z, F1.w,
                                  F2.x, F2.y, F2.z, F2.w,
                                  F3.x, F3.y, F3.z, F3.w };
#pragma unroll
            for (int dx = 0; dx < ND; ++dx)
#pragma unroll
                for (int j = 0; j < 8; ++j)
                    acc[dx][j] = fmaf(a[j], f[j + dx], acc[dx][j]);
        }
    }

    // ---- epilogue: scale by 1/C, coalesced float4 stores ----
    const float sc = 1.0f / 128.0f;
    float* op = out + (((size_t)b * NDD + (size_t)w * ND) * HH + (y0 + tr)) * WW + lb * 8;
#pragma unroll
    for (int dx = 0; dx < ND; ++dx) {
        float4 v0 = { acc[dx][0] * sc, acc[dx][1] * sc, acc[dx][2] * sc, acc[dx][3] * sc };
        float4 v1 = { acc[dx][4] * sc, acc[dx][5] * sc, acc[dx][6] * sc, acc[dx][7] * sc };
        *reinterpret_cast<float4*>(op + (size_t)dx * (HH * WW))     = v0;
        *reinterpret_cast<float4*>(op + (size_t)dx * (HH * WW) + 4) = v1;
    }
}

extern "C" void kernel_launch(void* const* d_in, const int* in_sizes, int n_in,
                              void* d_out, int out_size)
{
    (void)in_sizes; (void)n_in; (void)out_size;
    cudaFuncSetAttribute(corr_kernel,
                         cudaFuncAttributeMaxDynamicSharedMemorySize, SMEM_BYTES);
    const float* in1 = (const float*)d_in[0];
    const float* in2 = (const float*)d_in[1];
    float* out = (float*)d_out;
    corr_kernel<<<dim3(HH / TY, BB), THREADS, SMEM_BYTES>>>(in1, in2, out);
}

// round 16
// speedup vs baseline: 1.9965x; 1.9965x over previous
#include <cuda_runtime.h>
#include <cstdint>

// Correlation cost volume: B=8, C=128, H=W=128, max_disp=4 -> 81 displacements.
// out[b, dy*9+dx, y, x] = (1/C) sum_c in1[b,c,y,x] * in2[b,c,y+dy-4,x+dx-4] (zero pad)
//
// R16: barrier-free steady state.
//  - Block = (b, one output row y0). 9 warps, warp w = dy. Lane = 4 pixels.
//  - in1 row (all 128 channels, 64KB) loaded once at prologue (single barrier).
//  - in2: warp-private rows (warp w only ever needs gy = y0-4+w), streamed
//    through a private 8-deep cp.async ring; __syncwarp + wait_group only.
//  - All smem linear; A and F reads are lane-contiguous LDS.128 (conflict-free).
//  - Pure scalar FFMA, 36 accumulators/thread.

#define BB 8
#define CC 128
#define HH 128
#define WW 128
#define MD 4
#define ND 9
#define NDD 81
#define THREADS 288             // 9 warps
#define DEPTH 8                 // F ring stages (power of 2)

#define A_WORDS (CC * WW)               // 16384 floats = 64KB
#define F_ROWW 136                      // 34 quads: [pad4 | 128 | pad4]
#define F_STAGE_W (ND * F_ROWW)         // 1224 words per stage (all 9 warps)
#define SMEM_WORDS (A_WORDS + DEPTH * F_STAGE_W)    // 26176
#define SMEM_BYTES (SMEM_WORDS * 4)                 // 104704

__device__ __forceinline__ void cp16(uint32_t dst, const float* src, int srcsz) {
    asm volatile("cp.async.cg.shared.global [%0], [%1], 16, %2;\n"
                 :: "r"(dst), "l"(src), "r"(srcsz));
}
__device__ __forceinline__ void cp_commit() {
    asm volatile("cp.async.commit_group;\n");
}
#define CP_WAIT(n) asm volatile("cp.async.wait_group %0;\n" :: "n"(n))

__global__ __launch_bounds__(THREADS, 2)
void corr_kernel(const float* __restrict__ in1,
                 const float* __restrict__ in2,
                 float* __restrict__ out)
{
    extern __shared__ float sm[];
    const uint32_t smb = (uint32_t)__cvta_generic_to_shared(sm);

    const int y0 = blockIdx.x;          // output row
    const int b  = blockIdx.y;

    const int tid  = threadIdx.x;
    const int w    = tid >> 5;          // dy index 0..8
    const int lane = tid & 31;          // pixels 4*lane .. 4*lane+3

    const int gy   = y0 - MD + w;       // in2 row for this warp (all channels)
    const bool yok = (unsigned)gy < HH;

    // ---- zero the always-padding edge quads of this warp's F ring ----
    // quads 0 and 33 of each stage row; interior copies never touch them.
    if (lane < 2 * DEPTH) {
        int s = lane >> 1;
        int q = (lane & 1) * 33;
        float4* p = reinterpret_cast<float4*>(
            sm + A_WORDS + (s * ND + w) * F_ROWW + q * 4);
        *p = make_float4(0.f, 0.f, 0.f, 0.f);
    }

    // ---- prologue: in1 row, all channels, one cp.async group ----
    {
        const float* g1 = in1 + ((size_t)b * CC * HH + y0) * WW;
        for (int i = tid; i < A_WORDS / 4; i += THREADS) {      // quad index
            int c = i >> 5, q = i & 31;
            cp16(smb + 16u * (uint32_t)i, g1 + (size_t)c * (HH * WW) + 4 * q, 16);
        }
        cp_commit();
    }

    // ---- in2 source for this warp ----
    const float* g2;
    int oksz;
    if (yok) { g2 = in2 + ((size_t)b * CC * HH + gy) * WW + 4 * lane; oksz = 16; }
    else     { g2 = in2;                                              oksz = 0;  }

    const uint32_t fw = smb + 4u * (uint32_t)(A_WORDS + w * F_ROWW) + 16u * (lane + 1);
    const uint32_t fstep = 4u * F_STAGE_W;      // bytes per ring stage

    // prologue: issue F for channels 0..DEPTH-2 (7 groups)
#pragma unroll
    for (int c = 0; c < DEPTH - 1; ++c) {
        cp16(fw + (uint32_t)c * fstep, g2 + (size_t)c * (HH * WW), oksz);
        cp_commit();
    }

    CP_WAIT(DEPTH - 1);     // in1 group (oldest) complete for this thread
    __syncthreads();        // publish in1 to all warps (only block barrier)

    float acc[ND][4];
#pragma unroll
    for (int dx = 0; dx < ND; ++dx)
#pragma unroll
        for (int j = 0; j < 4; ++j) acc[dx][j] = 0.0f;

    const float* fbase = sm + A_WORDS + w * F_ROWW + 4 * lane;

#pragma unroll 2
    for (int c = 0; c < CC; ++c) {
        // issue F(c + DEPTH-1); empty group past the end keeps counts uniform
        int nc = c + DEPTH - 1;
        if (nc < CC)
            cp16(fw + (uint32_t)(nc & (DEPTH - 1)) * fstep,
                 g2 + (size_t)nc * (HH * WW), oksz);
        cp_commit();
        CP_WAIT(DEPTH - 1);     // F(c) resident (this warp's own copies)
        __syncwarp();

        // ---- compute channel c: 4 px, 9 dx ----
        const float* Ap = sm + c * WW + 4 * lane;
        float4 A4 = *reinterpret_cast<const float4*>(Ap);

        const float* Fp = fbase + (c & (DEPTH - 1)) * F_STAGE_W;
        float4 F0 = *reinterpret_cast<const float4*>(Fp);
        float4 F1 = *reinterpret_cast<const float4*>(Fp + 4);
        float4 F2 = *reinterpret_cast<const float4*>(Fp + 8);

        const float a[4]  = { A4.x, A4.y, A4.z, A4.w };
        const float f[12] = { F0.x, F0.y, F0.z, F0.w,
                              F1.x, F1.y, F1.z, F1.w,
                              F2.x, F2.y, F2.z, F2.w };
#pragma unroll
        for (int dx = 0; dx < ND; ++dx)
#pragma unroll
            for (int j = 0; j < 4; ++j)
                acc[dx][j] = fmaf(a[j], f[j + dx], acc[dx][j]);
    }

    // ---- epilogue: scale by 1/C, coalesced float4 stores ----
    const float sc = 1.0f / 128.0f;
    float* op = out + (((size_t)(b * NDD + w * ND)) * HH + y0) * WW + 4 * lane;
#pragma unroll
    for (int dx = 0; dx < ND; ++dx) {
        float4 v = { acc[dx][0] * sc, acc[dx][1] * sc,
                     acc[dx][2] * sc, acc[dx][3] * sc };
        *reinterpret_cast<float4*>(op + (size_t)dx * (HH * WW)) = v;
    }
}

extern "C" void kernel_launch(void* const* d_in, const int* in_sizes, int n_in,
                              void* d_out, int out_size)
{
    (void)in_sizes; (void)n_in; (void)out_size;
    cudaFuncSetAttribute(corr_kernel,
                         cudaFuncAttributeMaxDynamicSharedMemorySize, SMEM_BYTES);
    const float* in1 = (const float*)d_in[0];
    const float* in2 = (const float*)d_in[1];
    float* out = (float*)d_out;
    corr_kernel<<<dim3(HH, BB), THREADS, SMEM_BYTES>>>(in1, in2, out);
}

// round 17
// speedup vs baseline: 2.1047x; 1.0542x over previous
#include <cuda_runtime.h>
#include <cstdint>

// Correlation cost volume: B=8, C=128, H=W=128, max_disp=4 -> 81 displacements.
// out[b, dy*9+dx, y, x] = (1/C) sum_c in1[b,c,y,x] * in2[b,c,y+dy-4,x+dx-4] (zero pad)
//
// R17 = R16 (barrier-free: block = one output row, 9 warps = dy, lane = 4 px,
//            in1 row cached once, warp-private 8-deep cp.async F ring)
//       + channel loop fully unrolled by 8 (compile-time ring offsets)
//       + wait_group/__syncwarp per 2 channels instead of per channel.

#define BB 8
#define CC 128
#define HH 128
#define WW 128
#define MD 4
#define ND 9
#define NDD 81
#define THREADS 288             // 9 warps
#define DEPTH 8                 // F ring stages (one ring = one unroll block)

#define A_WORDS (CC * WW)               // 16384 floats = 64KB
#define F_ROWW 136                      // 34 quads: [pad4 | 128 | pad4]
#define F_STAGE_W (ND * F_ROWW)         // 1224 words per stage (all 9 warps)
#define SMEM_WORDS (A_WORDS + DEPTH * F_STAGE_W)    // 26176
#define SMEM_BYTES (SMEM_WORDS * 4)                 // 104704

#define HW (HH * WW)

__device__ __forceinline__ void cp16(uint32_t dst, const float* src, int srcsz) {
    asm volatile("cp.async.cg.shared.global [%0], [%1], 16, %2;\n"
                 :: "r"(dst), "l"(src), "r"(srcsz));
}
__device__ __forceinline__ void cp_commit() {
    asm volatile("cp.async.commit_group;\n");
}
#define CP_WAIT(n) asm volatile("cp.async.wait_group %0;\n" :: "n"(n))

__global__ __launch_bounds__(THREADS, 2)
void corr_kernel(const float* __restrict__ in1,
                 const float* __restrict__ in2,
                 float* __restrict__ out)
{
    extern __shared__ float sm[];
    const uint32_t smb = (uint32_t)__cvta_generic_to_shared(sm);

    const int y0 = blockIdx.x;          // output row
    const int b  = blockIdx.y;

    const int tid  = threadIdx.x;
    const int w    = tid >> 5;          // dy index 0..8
    const int lane = tid & 31;          // pixels 4*lane .. 4*lane+3

    const int gy   = y0 - MD + w;       // in2 row for this warp (all channels)
    const bool yok = (unsigned)gy < HH;

    // ---- zero the always-padding edge quads of this warp's F ring ----
    if (lane < 2 * DEPTH) {
        int s = lane >> 1;
        int q = (lane & 1) * 33;
        float4* p = reinterpret_cast<float4*>(
            sm + A_WORDS + (s * ND + w) * F_ROWW + q * 4);
        *p = make_float4(0.f, 0.f, 0.f, 0.f);
    }

    // ---- prologue: in1 row, all channels, one cp.async group ----
    {
        const float* g1 = in1 + ((size_t)b * CC * HH + y0) * WW;
        for (int i = tid; i < A_WORDS / 4; i += THREADS) {      // quad index
            int c = i >> 5, q = i & 31;
            cp16(smb + 16u * (uint32_t)i, g1 + (size_t)c * HW + 4 * q, 16);
        }
        cp_commit();
    }

    // ---- in2 source for this warp ----
    const float* g2;
    int oksz;
    if (yok) { g2 = in2 + ((size_t)b * CC * HH + gy) * WW + 4 * lane; oksz = 16; }
    else     { g2 = in2;                                              oksz = 0;  }

    const uint32_t fw = smb + 4u * (uint32_t)(A_WORDS + w * F_ROWW) + 16u * (lane + 1);
    const uint32_t fstep = 4u * F_STAGE_W;      // bytes per ring stage

    // prologue: issue F for channels 0..5 (6 groups)
#pragma unroll
    for (int c = 0; c < DEPTH - 2; ++c) {
        cp16(fw + (uint32_t)c * fstep, g2 + (size_t)c * HW, oksz);
        cp_commit();
    }

    CP_WAIT(6);             // in1 group (oldest) complete for this thread
    __syncthreads();        // publish in1 to all warps (only block barrier)

    float acc[ND][4];
#pragma unroll
    for (int dx = 0; dx < ND; ++dx)
#pragma unroll
        for (int j = 0; j < 4; ++j) acc[dx][j] = 0.0f;

    const float* Abase = sm + 4 * lane;                     // + c*WW
    const float* Fbase = sm + A_WORDS + w * F_ROWW + 4 * lane;  // + slot*F_STAGE_W

    for (int cb = 0; cb < CC; cb += DEPTH) {
        const float* Ac = Abase + cb * WW;
        const float* g2c = g2 + (size_t)cb * HW;
#pragma unroll
        for (int u = 0; u < DEPTH; u += 2) {
            // issue F(cb+u+6), F(cb+u+7): ring slots (u+6)&7, (u+7)&7 (const)
            {
                int n0 = cb + u + 6;
                if (n0 < CC)
                    cp16(fw + (uint32_t)((u + 6) & 7) * fstep,
                         g2c + (size_t)(u + 6) * HW, oksz);
                cp_commit();
                int n1 = cb + u + 7;
                if (n1 < CC)
                    cp16(fw + (uint32_t)((u + 7) & 7) * fstep,
                         g2c + (size_t)(u + 7) * HW, oksz);
                cp_commit();
            }
            CP_WAIT(6);         // F(cb+u), F(cb+u+1) resident
            __syncwarp();

            // ---- compute channels cb+u and cb+u+1 (const smem offsets) ----
#pragma unroll
            for (int v = 0; v < 2; ++v) {
                const int uu = u + v;
                float4 A4 = *reinterpret_cast<const float4*>(Ac + uu * WW);
                const float* Fp = Fbase + (uu & 7) * F_STAGE_W;
                float4 F0 = *reinterpret_cast<const float4*>(Fp);
                float4 F1 = *reinterpret_cast<const float4*>(Fp + 4);
                float4 F2 = *reinterpret_cast<const float4*>(Fp + 8);

                const float a[4]  = { A4.x, A4.y, A4.z, A4.w };
                const float f[12] = { F0.x, F0.y, F0.z, F0.w,
                                      F1.x, F1.y, F1.z, F1.w,
                                      F2.x, F2.y, F2.z, F2.w };
#pragma unroll
                for (int dx = 0; dx < ND; ++dx)
#pragma unroll
                    for (int j = 0; j < 4; ++j)
                        acc[dx][j] = fmaf(a[j], f[j + dx], acc[dx][j]);
            }
        }
    }

    // ---- epilogue: scale by 1/C, coalesced float4 stores ----
    const float sc = 1.0f / 128.0f;
    float* op = out + (((size_t)(b * NDD + w * ND)) * HH + y0) * WW + 4 * lane;
#pragma unroll
    for (int dx = 0; dx < ND; ++dx) {
        float4 v = { acc[dx][0] * sc, acc[dx][1] * sc,
                     acc[dx][2] * sc, acc[dx][3] * sc };
        *reinterpret_cast<float4*>(op + (size_t)dx * HW) = v;
    }
}

extern "C" void kernel_launch(void* const* d_in, const int* in_sizes, int n_in,
                              void* d_out, int out_size)
{
    (void)in_sizes; (void)n_in; (void)out_size;
    cudaFuncSetAttribute(corr_kernel,
                         cudaFuncAttributeMaxDynamicSharedMemorySize, SMEM_BYTES);
    const float* in1 = (const float*)d_in[0];
    const float* in2 = (const float*)d_in[1];
    float* out = (float*)d_out;
    corr_kernel<<<dim3(HH, BB), THREADS, SMEM_BYTES>>>(in1, in2, out);
}